// round 2
// baseline (speedup 1.0000x reference)
#include <cuda_runtime.h>
#include <cuda_bf16.h>
#include <math.h>

#define HIDDEN 768
#define HEADS  12
#define DK     64
#define BATCH  8
#define SEQ    512
#define ORDERS 3
#define NEGV   -1e9f

// ---------------- scratch (device globals; no allocs allowed) ----------------
__device__ float g_qh[BATCH * HEADS * SEQ * DK];     // [b][h][n][d], pre-scaled by 1/8
__device__ float g_kh[BATCH * HEADS * SEQ * DK];
__device__ float g_vh[BATCH * HEADS * SEQ * DK];
__device__ float g_atted[BATCH * SEQ * HIDDEN];      // [b*512+n][h*64+d]
__device__ float g_pooled[BATCH * HIDDEN];
__device__ float g_alphas[BATCH * ORDERS];
__device__ int   g_mask_mode;                        // 0=uint8, 1=int32, 2=float32

// ---------------- mask dtype detection (runs on device, graph-safe) ---------
__global__ void detect_mask_mode(const unsigned* __restrict__ m) {
    __shared__ int sflags;
    if (threadIdx.x == 0) sflags = 0;
    __syncthreads();
    int local = 0;
    for (int i = threadIdx.x; i < 16384; i += 256) {
        unsigned w = m[i];
        if (w == 0x3F800000u) local |= 1;          // float32 1.0f
        else if (w != 0u && w != 1u) local |= 2;   // packed uint8 bytes
    }
    if (local) atomicOr(&sflags, local);
    __syncthreads();
    if (threadIdx.x == 0)
        g_mask_mode = (sflags & 1) ? 2 : ((sflags & 2) ? 0 : 1);
}

// ---------------- routing kernel 1: masked attention pooling ----------------
__global__ __launch_bounds__(256) void route_pool(const float* __restrict__ v,
                                                  const float* __restrict__ pool_w,
                                                  const float* __restrict__ pool_b) {
    int b = blockIdx.x;
    int tid = threadIdx.x, warp = tid >> 5, lane = tid & 31;
    __shared__ float sc[SEQ];
    __shared__ float red[8], red2[8];
    __shared__ float pw[HIDDEN];
    for (int d = tid; d < HIDDEN; d += 256) pw[d] = pool_w[d];
    __syncthreads();

    // scores: one warp per row n
    for (int n = warp; n < SEQ; n += 8) {
        const float* vp = v + ((size_t)b * SEQ + n) * HIDDEN;
        float dot = 0.f, asum = 0.f;
        for (int d = lane; d < HIDDEN; d += 32) {
            float x = vp[d];
            dot += x * pw[d];
            asum += fabsf(x);
        }
        #pragma unroll
        for (int o = 16; o; o >>= 1) {
            dot  += __shfl_xor_sync(0xffffffffu, dot, o);
            asum += __shfl_xor_sync(0xffffffffu, asum, o);
        }
        if (lane == 0) sc[n] = (asum == 0.f) ? NEGV : (dot + pool_b[0]);
    }
    __syncthreads();

    // softmax over 512
    float m = fmaxf(sc[tid], sc[tid + 256]);
    #pragma unroll
    for (int o = 16; o; o >>= 1) m = fmaxf(m, __shfl_xor_sync(0xffffffffu, m, o));
    if (lane == 0) red[warp] = m;
    __syncthreads();
    if (tid == 0) {
        float t = red[0];
        #pragma unroll
        for (int i = 1; i < 8; i++) t = fmaxf(t, red[i]);
        red[0] = t;
    }
    __syncthreads();
    m = red[0];
    float e0 = __expf(sc[tid] - m), e1 = __expf(sc[tid + 256] - m);
    float s = e0 + e1;
    #pragma unroll
    for (int o = 16; o; o >>= 1) s += __shfl_xor_sync(0xffffffffu, s, o);
    if (lane == 0) red2[warp] = s;
    __syncthreads();
    if (tid == 0) {
        float t = 0.f;
        #pragma unroll
        for (int i = 0; i < 8; i++) t += red2[i];
        red2[0] = t;
    }
    __syncthreads();
    float inv = 1.f / red2[0];
    sc[tid] = e0 * inv;
    sc[tid + 256] = e1 * inv;
    __syncthreads();

    // pooled[d] = sum_n v[b,n,d] * p[n]   (coalesced over d)
    float a0 = 0.f, a1 = 0.f, a2 = 0.f;
    for (int n = 0; n < SEQ; n++) {
        float p = sc[n];
        const float* vp = v + ((size_t)b * SEQ + n) * HIDDEN;
        a0 += vp[tid]       * p;
        a1 += vp[tid + 256] * p;
        a2 += vp[tid + 512] * p;
    }
    g_pooled[b * HIDDEN + tid]       = a0;
    g_pooled[b * HIDDEN + tid + 256] = a1;
    g_pooled[b * HIDDEN + tid + 512] = a2;
}

// ---------------- routing kernel 2: MLP + softmax -> alphas ----------------
__global__ __launch_bounds__(384) void route_mlp(const float* __restrict__ w1,
                                                 const float* __restrict__ w2,
                                                 const float* __restrict__ b2) {
    int b = blockIdx.x, tid = threadIdx.x;
    __shared__ float pl[HIDDEN];
    __shared__ float pred[12 * 3];
    for (int d = tid; d < HIDDEN; d += 384) pl[d] = g_pooled[b * HIDDEN + d];
    __syncthreads();
    float acc = 0.f;
    for (int k = 0; k < HIDDEN; k++) acc += pl[k] * w1[k * 384 + tid];
    float hv = fmaxf(acc, 0.f);
    float p0 = hv * w2[tid * 3 + 0];
    float p1 = hv * w2[tid * 3 + 1];
    float p2 = hv * w2[tid * 3 + 2];
    #pragma unroll
    for (int o = 16; o; o >>= 1) {
        p0 += __shfl_xor_sync(0xffffffffu, p0, o);
        p1 += __shfl_xor_sync(0xffffffffu, p1, o);
        p2 += __shfl_xor_sync(0xffffffffu, p2, o);
    }
    int warp = tid >> 5;
    if ((tid & 31) == 0) { pred[warp * 3] = p0; pred[warp * 3 + 1] = p1; pred[warp * 3 + 2] = p2; }
    __syncthreads();
    if (tid == 0) {
        float l0 = b2[0], l1 = b2[1], l2 = b2[2];
        for (int w = 0; w < 12; w++) { l0 += pred[w * 3]; l1 += pred[w * 3 + 1]; l2 += pred[w * 3 + 2]; }
        float mm = fmaxf(l0, fmaxf(l1, l2));
        float e0 = __expf(l0 - mm), e1 = __expf(l1 - mm), e2 = __expf(l2 - mm);
        float z = e0 + e1 + e2;
        g_alphas[b * 3 + 0] = e0 / z;
        g_alphas[b * 3 + 1] = e1 / z;
        g_alphas[b * 3 + 2] = e2 / z;
    }
}

// ---------------- 64x64 tiled fp32 GEMM, C = (X W + bias) * scale -----------
// headlayout=1: out[((b*12+h)*512+n)*64+d]  (row i=b*512+n, col j=h*64+d)
// headlayout=0: out[i*Ncols + j]
__global__ __launch_bounds__(256) void gemm64(const float* __restrict__ X,
                                              const float* __restrict__ W,
                                              const float* __restrict__ bias,
                                              float* __restrict__ out,
                                              int Kdim, int Ncols,
                                              float scale, int headlayout) {
    __shared__ float Xs[16][64];   // [k][row]  (transposed)
    __shared__ float Ws[16][64];   // [k][col]
    int tid = threadIdx.x;
    int bn = blockIdx.x, bm = blockIdx.y;
    int tr = tid >> 4, tc = tid & 15;
    int row0 = bm * 64, col0 = bn * 64;
    int lxr = tid >> 2;            // 0..63
    int lxk = (tid & 3) * 4;       // 0,4,8,12
    int lwk = tid >> 4;            // 0..15
    int lwc = (tid & 15) * 4;      // 0..60

    float acc[4][4] = {};
    for (int kt = 0; kt < Kdim; kt += 16) {
        float4 xv = *(const float4*)(X + (size_t)(row0 + lxr) * Kdim + kt + lxk);
        float4 wv = *(const float4*)(W + (size_t)(kt + lwk) * Ncols + col0 + lwc);
        __syncthreads();
        Xs[lxk + 0][lxr] = xv.x;
        Xs[lxk + 1][lxr] = xv.y;
        Xs[lxk + 2][lxr] = xv.z;
        Xs[lxk + 3][lxr] = xv.w;
        *(float4*)&Ws[lwk][lwc] = wv;
        __syncthreads();
        #pragma unroll
        for (int kk = 0; kk < 16; kk++) {
            float4 a4 = *(const float4*)&Xs[kk][tr * 4];
            float4 b4 = *(const float4*)&Ws[kk][tc * 4];
            float av[4] = {a4.x, a4.y, a4.z, a4.w};
            float bv[4] = {b4.x, b4.y, b4.z, b4.w};
            #pragma unroll
            for (int i = 0; i < 4; i++)
                #pragma unroll
                for (int j = 0; j < 4; j++)
                    acc[i][j] += av[i] * bv[j];
        }
    }
    // epilogue
    int gj0 = col0 + tc * 4;
    float4 bb = *(const float4*)(bias + gj0);
    float bvv[4] = {bb.x, bb.y, bb.z, bb.w};
    #pragma unroll
    for (int i = 0; i < 4; i++) {
        int gi = row0 + tr * 4 + i;
        float4 o4;
        o4.x = (acc[i][0] + bvv[0]) * scale;
        o4.y = (acc[i][1] + bvv[1]) * scale;
        o4.z = (acc[i][2] + bvv[2]) * scale;
        o4.w = (acc[i][3] + bvv[3]) * scale;
        if (headlayout) {
            int b = gi >> 9, n = gi & 511;
            int h = gj0 >> 6, d = gj0 & 63;
            *(float4*)&out[(((size_t)b * HEADS + h) * SEQ + n) * DK + d] = o4;
        } else {
            *(float4*)&out[(size_t)gi * Ncols + gj0] = o4;
        }
    }
}

// ---------------- fused attention: scores, 3 masked softmaxes, mix, A@V -----
#define SPITCH 516
#define QKPITCH 68
#define ATTN_SMEM ((64 * SPITCH + 64 * QKPITCH + 64 * QKPITCH) * 4 + 64 * 48 * 4 + 16)

__global__ __launch_bounds__(256) void attn_kernel(const void* __restrict__ masks) {
    extern __shared__ float sm[];
    float* S   = sm;                         // 64 x 516
    float* Qt  = S + 64 * SPITCH;            // transposed [d][r], pitch 68
    float* KVt = Qt + 64 * QKPITCH;          // K transposed / V natural
    unsigned* mw = (unsigned*)(KVt + 64 * QKPITCH);  // 64 x 48 packed mask bits
    float* salpha = (float*)(mw + 64 * 48);

    int rt = blockIdx.x, h = blockIdx.y, b = blockIdx.z;
    int tid = threadIdx.x;
    int tr = tid >> 4, tc = tid & 15;
    int mode = g_mask_mode;

    const float* Qg = g_qh + (((size_t)(b * HEADS + h)) * SEQ + rt * 64) * DK;
    const float* Kg = g_kh + ((size_t)(b * HEADS + h)) * SEQ * DK;
    const float* Vg = g_vh + ((size_t)(b * HEADS + h)) * SEQ * DK;

    if (tid < 3) salpha[tid] = g_alphas[b * 3 + tid];
    for (int idx = tid; idx < 4096; idx += 256) {
        int r = idx >> 6, d = idx & 63;
        Qt[d * QKPITCH + r] = Qg[idx];
    }

    // ---- phase 1: S[64][512] = Q K^T (q pre-scaled by 1/8) ----
    for (int mt = 0; mt < 8; mt++) {
        __syncthreads();
        for (int idx = tid; idx < 4096; idx += 256) {
            int r = idx >> 6, d = idx & 63;
            KVt[d * QKPITCH + r] = Kg[mt * 4096 + idx];
        }
        __syncthreads();
        float a[4][4] = {};
        #pragma unroll 16
        for (int kk = 0; kk < 64; kk++) {
            float4 q4 = *(const float4*)&Qt[kk * QKPITCH + tr * 4];
            float4 k4 = *(const float4*)&KVt[kk * QKPITCH + tc * 4];
            float qa[4] = {q4.x, q4.y, q4.z, q4.w};
            float ka[4] = {k4.x, k4.y, k4.z, k4.w};
            #pragma unroll
            for (int i = 0; i < 4; i++)
                #pragma unroll
                for (int j = 0; j < 4; j++)
                    a[i][j] += qa[i] * ka[j];
        }
        #pragma unroll
        for (int i = 0; i < 4; i++)
            *(float4*)&S[(tr * 4 + i) * SPITCH + mt * 64 + tc * 4] =
                make_float4(a[i][0], a[i][1], a[i][2], a[i][3]);
    }
    __syncthreads();

    // ---- phase 2: per-row: E = exp(s - rowmax); Z_l over !mask_l; combine ----
    int warp = tid >> 5, lane = tid & 31;
    const unsigned char* m8 = (const unsigned char*)masks;
    const int*           mi = (const int*)masks;
    const float*         mf = (const float*)masks;
    for (int r = warp * 8; r < warp * 8 + 8; r++) {
        float* Sr = S + r * SPITCH;
        int n = rt * 64 + r;
        size_t off0 = ((size_t)(0 * BATCH + b) * SEQ + n) * SEQ;
        size_t off1 = ((size_t)(1 * BATCH + b) * SEQ + n) * SEQ;
        size_t off2 = ((size_t)(2 * BATCH + b) * SEQ + n) * SEQ;

        float mx = -1e30f;
        #pragma unroll
        for (int it = 0; it < 16; it++) mx = fmaxf(mx, Sr[it * 32 + lane]);
        #pragma unroll
        for (int o = 16; o; o >>= 1) mx = fmaxf(mx, __shfl_xor_sync(0xffffffffu, mx, o));

        float z0 = 0.f, z1 = 0.f, z2 = 0.f;
        #pragma unroll
        for (int it = 0; it < 16; it++) {
            int c = it * 32 + lane;
            float e = __expf(Sr[c] - mx);
            Sr[c] = e;
            bool b0, b1, b2;
            if (mode == 1) {
                b0 = mi[off0 + c] != 0;  b1 = mi[off1 + c] != 0;  b2 = mi[off2 + c] != 0;
            } else if (mode == 2) {
                b0 = mf[off0 + c] != 0.f; b1 = mf[off1 + c] != 0.f; b2 = mf[off2 + c] != 0.f;
            } else {
                b0 = m8[off0 + c] != 0;  b1 = m8[off1 + c] != 0;  b2 = m8[off2 + c] != 0;
            }
            unsigned w0 = __ballot_sync(0xffffffffu, b0);
            unsigned w1 = __ballot_sync(0xffffffffu, b1);
            unsigned w2 = __ballot_sync(0xffffffffu, b2);
            if (!b0) z0 += e;
            if (!b1) z1 += e;
            if (!b2) z2 += e;
            if (lane == 0) {
                mw[r * 48 + it * 3 + 0] = w0;
                mw[r * 48 + it * 3 + 1] = w1;
                mw[r * 48 + it * 3 + 2] = w2;
            }
        }
        #pragma unroll
        for (int o = 16; o; o >>= 1) {
            z0 += __shfl_xor_sync(0xffffffffu, z0, o);
            z1 += __shfl_xor_sync(0xffffffffu, z1, o);
            z2 += __shfl_xor_sync(0xffffffffu, z2, o);
        }
        __syncwarp();
        float wa0 = salpha[0] / z0, wa1 = salpha[1] / z1, wa2 = salpha[2] / z2;
        #pragma unroll
        for (int it = 0; it < 16; it++) {
            int c = it * 32 + lane;
            unsigned w0 = mw[r * 48 + it * 3 + 0];
            unsigned w1 = mw[r * 48 + it * 3 + 1];
            unsigned w2 = mw[r * 48 + it * 3 + 2];
            float coef = (((w0 >> lane) & 1) ? 0.f : wa0)
                       + (((w1 >> lane) & 1) ? 0.f : wa1)
                       + (((w2 >> lane) & 1) ? 0.f : wa2);
            Sr[c] *= coef;
        }
    }

    // ---- phase 3: O[64][64] = A[64][512] @ V[512][64] ----
    float* Vs = KVt;  // natural layout, pitch 64
    float o[4][4] = {};
    for (int mt = 0; mt < 8; mt++) {
        __syncthreads();
        const float4* src = (const float4*)(Vg + mt * 4096);
        float4* dst = (float4*)Vs;
        for (int idx = tid; idx < 1024; idx += 256) dst[idx] = src[idx];
        __syncthreads();
        #pragma unroll 8
        for (int mm = 0; mm < 64; mm++) {
            float a0 = S[(tr * 4 + 0) * SPITCH + mt * 64 + mm];
            float a1 = S[(tr * 4 + 1) * SPITCH + mt * 64 + mm];
            float a2 = S[(tr * 4 + 2) * SPITCH + mt * 64 + mm];
            float a3 = S[(tr * 4 + 3) * SPITCH + mt * 64 + mm];
            float4 v4 = *(const float4*)&Vs[mm * 64 + tc * 4];
            float vv[4] = {v4.x, v4.y, v4.z, v4.w};
            float aa[4] = {a0, a1, a2, a3};
            #pragma unroll
            for (int i = 0; i < 4; i++)
                #pragma unroll
                for (int j = 0; j < 4; j++)
                    o[i][j] += aa[i] * vv[j];
        }
    }
    // atted layout: [b*512+n][h*64+d]
    #pragma unroll
    for (int i = 0; i < 4; i++) {
        int row = tr * 4 + i;
        size_t off = ((size_t)(b * SEQ + rt * 64 + row) * HEADS + h) * DK + tc * 4;
        *(float4*)&g_atted[off] = make_float4(o[i][0], o[i][1], o[i][2], o[i][3]);
    }
}

// ---------------- launch ----------------
extern "C" void kernel_launch(void* const* d_in, const int* in_sizes, int n_in,
                              void* d_out, int out_size) {
    const float* v = (const float*)d_in[0];
    const float* k = (const float*)d_in[1];
    const float* q = (const float*)d_in[2];
    const void*  masks = d_in[3];
    // d_in[4]=tau, d_in[5]=training : unused by inference path
    const float* Wv = (const float*)d_in[6];
    const float* bv = (const float*)d_in[7];
    const float* Wk = (const float*)d_in[8];
    const float* bk = (const float*)d_in[9];
    const float* Wq = (const float*)d_in[10];
    const float* bq = (const float*)d_in[11];
    const float* Wm = (const float*)d_in[12];
    const float* bm = (const float*)d_in[13];
    const float* pool_w = (const float*)d_in[14];
    const float* pool_b = (const float*)d_in[15];
    const float* w1 = (const float*)d_in[16];
    const float* w2 = (const float*)d_in[17];
    const float* b2 = (const float*)d_in[18];
    float* out = (float*)d_out;

    float *qh, *kh, *vh, *atted;
    cudaGetSymbolAddress((void**)&qh, g_qh);
    cudaGetSymbolAddress((void**)&kh, g_kh);
    cudaGetSymbolAddress((void**)&vh, g_vh);
    cudaGetSymbolAddress((void**)&atted, g_atted);

    cudaFuncSetAttribute(attn_kernel, cudaFuncAttributeMaxDynamicSharedMemorySize, ATTN_SMEM);

    detect_mask_mode<<<1, 256>>>((const unsigned*)masks);
    route_pool<<<BATCH, 256>>>(v, pool_w, pool_b);
    route_mlp<<<BATCH, 384>>>(w1, w2, b2);

    dim3 gg(HIDDEN / 64, (BATCH * SEQ) / 64);  // (12, 64)
    gemm64<<<gg, 256>>>(q, Wq, bq, qh, HIDDEN, HIDDEN, 0.125f, 1);
    gemm64<<<gg, 256>>>(k, Wk, bk, kh, HIDDEN, HIDDEN, 1.f, 1);
    gemm64<<<gg, 256>>>(v, Wv, bv, vh, HIDDEN, HIDDEN, 1.f, 1);

    attn_kernel<<<dim3(SEQ / 64, HEADS, BATCH), 256, ATTN_SMEM>>>(masks);

    gemm64<<<gg, 256>>>(atted, Wm, bm, out, HIDDEN, HIDDEN, 1.f, 0);
}